// round 15
// baseline (speedup 1.0000x reference)
#include <cuda_runtime.h>
#include <cuda_fp16.h>
#include <cstdint>

// Problem constants
#define Bb 8
#define Ss 2048
#define Dd 512
#define Qq 8
#define Kk 1024
#define Mm (Bb * Ss)   // 16384 tokens
#define HALF_M (Mm / 2)
#define MARGIN 10.0f

// Scratch (no cudaMalloc allowed)
__device__ float   g_residual[Mm * Dd];   // 32 MB fp32 residual
__device__ int8_t  g_res8[Mm * Dd];       //  8 MB int8 residual
__device__ int8_t  g_cb8[Qq * Kk * Dd];   //  4 MB int8 codebooks
__device__ float   g_scaleA[Mm];          // per-token scale
__device__ float   g_scaleB[Qq * Kk];     // per-code scale
__device__ __half  g_dist[Mm * Kk];       // 32 MB approx distances (fp16)
__device__ float   g_c2[Qq * Kk];
__device__ float   g_loss[Qq];

// ---------------------------------------------------------------------------
// helpers
// ---------------------------------------------------------------------------
__device__ __forceinline__ uint32_t smem_u32(const void* p) {
    uint32_t a;
    asm("{ .reg .u64 t; cvta.to.shared.u64 t, %1; cvt.u32.u64 %0, t; }"
        : "=r"(a) : "l"(p));
    return a;
}
__device__ __forceinline__ void cp16(uint32_t sa, const void* g) {
    asm volatile("cp.async.cg.shared.global [%0], [%1], 16;"
                 :: "r"(sa), "l"(g) : "memory");
}
__device__ __forceinline__ void cp_commit() {
    asm volatile("cp.async.commit_group;" ::: "memory");
}
__device__ __forceinline__ void cp_wait0() {
    asm volatile("cp.async.wait_group 0;" ::: "memory");
}
__device__ __forceinline__ void ldsm4(uint32_t* r, uint32_t addr) {
    asm volatile("ldmatrix.sync.aligned.m8n8.x4.shared.b16 {%0,%1,%2,%3}, [%4];"
                 : "=r"(r[0]), "=r"(r[1]), "=r"(r[2]), "=r"(r[3])
                 : "r"(addr));
}
// int8 inputs, s32 accumulators
__device__ __forceinline__ void mma_s8(int* c, const uint32_t* a,
                                       uint32_t b0, uint32_t b1) {
    asm volatile(
        "mma.sync.aligned.m16n8k32.row.col.s32.s8.s8.s32 "
        "{%0,%1,%2,%3}, {%4,%5,%6,%7}, {%8,%9}, {%0,%1,%2,%3};"
        : "+r"(c[0]), "+r"(c[1]), "+r"(c[2]), "+r"(c[3])
        : "r"(a[0]), "r"(a[1]), "r"(a[2]), "r"(a[3]), "r"(b0), "r"(b1));
}
__device__ __forceinline__ int clamp127(int v) {
    return v < -127 ? -127 : (v > 127 ? 127 : v);
}
__device__ __forceinline__ uint32_t pack_s8(float4 v, float inv) {
    int b0 = clamp127(__float2int_rn(v.x * inv));
    int b1 = clamp127(__float2int_rn(v.y * inv));
    int b2 = clamp127(__float2int_rn(v.z * inv));
    int b3 = clamp127(__float2int_rn(v.w * inv));
    return (b0 & 0xFF) | ((b1 & 0xFF) << 8) | ((b2 & 0xFF) << 16)
         | ((b3 & 0xFF) << 24);
}
__device__ __forceinline__ float max4abs(float4 v) {
    return fmaxf(fmaxf(fabsf(v.x), fabsf(v.y)), fmaxf(fabsf(v.z), fabsf(v.w)));
}

// ---------------------------------------------------------------------------
// init: residual=x (fp32), res8=quant(x), scaleA  — one warp per token
// ---------------------------------------------------------------------------
__global__ void init_q_kernel(const float* __restrict__ x,
                              float* __restrict__ residual,
                              int8_t* __restrict__ res8,
                              float* __restrict__ scaleA)
{
    const int warp = threadIdx.x >> 5, lane = threadIdx.x & 31;
    const int token = blockIdx.x * 8 + warp;
    const float4* xp = (const float4*)(x + (size_t)token * Dd);
    float4* rp = (float4*)(residual + (size_t)token * Dd);
    uint32_t* r8 = (uint32_t*)(res8 + (size_t)token * Dd);

    float4 v[4];
    float mx = 0.0f;
    #pragma unroll
    for (int j = 0; j < 4; ++j) {
        v[j] = xp[lane + 32 * j];
        rp[lane + 32 * j] = v[j];
        mx = fmaxf(mx, max4abs(v[j]));
    }
    #pragma unroll
    for (int o = 16; o; o >>= 1) mx = fmaxf(mx, __shfl_xor_sync(~0u, mx, o));
    const float sc  = mx / 127.0f;
    const float inv = mx > 0.0f ? 127.0f / mx : 0.0f;
    #pragma unroll
    for (int j = 0; j < 4; ++j)
        r8[lane + 32 * j] = pack_s8(v[j], inv);
    if (lane == 0) scaleA[token] = sc;
}

// codebook quantize: one warp per code row; also c2 (fp32 exact)
__global__ void conv_q_kernel(const float* __restrict__ cb,
                              int8_t* __restrict__ cb8,
                              float* __restrict__ scaleB,
                              float* __restrict__ c2)
{
    const int warp = threadIdx.x >> 5, lane = threadIdx.x & 31;
    const int row = blockIdx.x * 8 + warp;
    const float4* cp = (const float4*)(cb + (size_t)row * Dd);
    uint32_t* c8 = (uint32_t*)(cb8 + (size_t)row * Dd);

    float4 v[4];
    float mx = 0.0f, ss = 0.0f;
    #pragma unroll
    for (int j = 0; j < 4; ++j) {
        v[j] = cp[lane + 32 * j];
        mx = fmaxf(mx, max4abs(v[j]));
        ss += v[j].x * v[j].x + v[j].y * v[j].y + v[j].z * v[j].z + v[j].w * v[j].w;
    }
    #pragma unroll
    for (int o = 16; o; o >>= 1) {
        mx = fmaxf(mx, __shfl_xor_sync(~0u, mx, o));
        ss += __shfl_xor_sync(~0u, ss, o);
    }
    const float sc  = mx / 127.0f;
    const float inv = mx > 0.0f ? 127.0f / mx : 0.0f;
    #pragma unroll
    for (int j = 0; j < 4; ++j)
        c8[lane + 32 * j] = pack_s8(v[j], inv);
    if (lane == 0) { scaleB[row] = sc; c2[row] = ss; }
}

// ---------------------------------------------------------------------------
// int8 mma.sync GEMM (s32 acc) -> approx distances (fp16 stores).
// CTA 128x128, 4 k-tiles of 128 bytes, 8 warps of 32x64, double-buffered
// cp.async, one sync per k-tile.
// dist[m][n] = fp16( c2[n] - 2*sA[m]*sB[n]*idot )
// ---------------------------------------------------------------------------
#define GEMM_SMEM 65536   // 2 bufs * (A 16KB + B 16KB)

__global__ __launch_bounds__(256, 2)
void gemm_dist_kernel(const int8_t* __restrict__ A8,
                      const int8_t* __restrict__ B8,
                      const float* __restrict__ sA,
                      const float* __restrict__ sB,
                      const float* __restrict__ c2,
                      __half* __restrict__ dist)
{
    extern __shared__ char sm[];
    const uint32_t smb   = smem_u32(sm);
    const uint32_t Abase = smb;           // [2][16384]
    const uint32_t Bbase = smb + 32768;   // [2][16384]

    const int tid  = threadIdx.x;
    const int lane = tid & 31;
    const int warp = tid >> 5;
    const int bm = blockIdx.x * 128;
    const int bn = blockIdx.y * 128;
    const int wm = (warp & 3) * 32;
    const int wn = (warp >> 2) * 64;

    const char* gA = (const char*)(A8 + (size_t)bm * Dd);
    const char* gB = (const char*)(B8 + (size_t)bn * Dd);

    int acc[2][8][4];
    #pragma unroll
    for (int mi = 0; mi < 2; ++mi)
        #pragma unroll
        for (int ni = 0; ni < 8; ++ni)
            #pragma unroll
            for (int j = 0; j < 4; ++j) acc[mi][ni][j] = 0;

    #define LOAD_TILE(kt, buf)                                                  \
        {                                                                       \
            _Pragma("unroll")                                                   \
            for (int i = 0; i < 4; ++i) {                                       \
                int u = tid + 256 * i;                                          \
                int row = u >> 3, ch = u & 7;                                   \
                uint32_t so = (uint32_t)(row * 128 + ((ch ^ (row & 7)) * 16));  \
                size_t go = (size_t)row * Dd + (kt) * 128 + ch * 16;            \
                cp16(Abase + (buf) * 16384 + so, gA + go);                      \
                cp16(Bbase + (buf) * 16384 + so, gB + go);                      \
            }                                                                   \
            cp_commit();                                                        \
        }

    LOAD_TILE(0, 0);

    for (int kt = 0; kt < 4; ++kt) {
        const int buf = kt & 1;
        cp_wait0();
        __syncthreads();
        if (kt < 3) LOAD_TILE(kt + 1, buf ^ 1);

        #pragma unroll
        for (int s = 0; s < 4; ++s) {
            uint32_t a[2][4], b[4][4];
            const int ch = s * 2 + (lane >> 4);
            #pragma unroll
            for (int mi = 0; mi < 2; ++mi) {
                int row = wm + mi * 16 + (lane & 15);
                ldsm4(a[mi], Abase + buf * 16384 + row * 128 +
                             ((ch ^ (row & 7)) * 16));
            }
            #pragma unroll
            for (int nj = 0; nj < 4; ++nj) {
                int row = wn + nj * 16 + (lane & 15);
                ldsm4(b[nj], Bbase + buf * 16384 + row * 128 +
                             ((ch ^ (row & 7)) * 16));
            }
            #pragma unroll
            for (int mi = 0; mi < 2; ++mi)
                #pragma unroll
                for (int ni = 0; ni < 8; ++ni)
                    mma_s8(acc[mi][ni], a[mi],
                           b[ni >> 1][ni & 1], b[ni >> 1][(ni & 1) + 2]);
        }
        __syncthreads();
    }

    // epilogue: d = c2[n] - 2*sA*sB*idot, fp16 stores
    const int g = lane >> 2, t4 = lane & 3;
    #pragma unroll
    for (int mi = 0; mi < 2; ++mi) {
        const int m0 = bm + wm + mi * 16 + g;
        const float sa0 = -2.0f * __ldg(sA + m0);
        const float sa1 = -2.0f * __ldg(sA + m0 + 8);
        #pragma unroll
        for (int ni = 0; ni < 8; ++ni) {
            const int n = bn + wn + ni * 8 + 2 * t4;
            float2 cc = *(const float2*)(c2 + n);
            float2 sb = *(const float2*)(sB + n);
            float d00 = fmaf(sa0 * sb.x, (float)acc[mi][ni][0], cc.x);
            float d01 = fmaf(sa0 * sb.y, (float)acc[mi][ni][1], cc.y);
            float d10 = fmaf(sa1 * sb.x, (float)acc[mi][ni][2], cc.x);
            float d11 = fmaf(sa1 * sb.y, (float)acc[mi][ni][3], cc.y);
            *(__half2*)(dist + (size_t)m0 * Kk + n)       = __floats2half2_rn(d00, d01);
            *(__half2*)(dist + (size_t)(m0 + 8) * Kk + n) = __floats2half2_rn(d10, d11);
        }
    }
    #undef LOAD_TILE
}

// ---------------------------------------------------------------------------
// Fused refine + update: warp per token (pointers pre-offset to token half).
// Scan fp16 dists, exact fp32 rescore within MARGIN, first-index tie-break,
// then residual update (fp32 + int8/scale for next stage) + loss + index.
// ---------------------------------------------------------------------------
__global__ __launch_bounds__(256)
void refine_update_kernel(const __half* __restrict__ dist,
                          float* __restrict__ R,
                          int8_t* __restrict__ R8w,
                          float* __restrict__ scaleAw,
                          const float* __restrict__ C,
                          const float* __restrict__ c2,
                          float* __restrict__ out_idx,
                          float* __restrict__ loss,
                          int qstage)
{
    const int warp = threadIdx.x >> 5, lane = threadIdx.x & 31;
    const int token = blockIdx.x * 8 + warp;

    // scan fp16 distances: 4 x uint4 per lane = 32 halves
    const uint4* dp = (const uint4*)(dist + (size_t)token * Kk);
    float v[32];
    float vmin = 3.4e38f;
    #pragma unroll
    for (int i = 0; i < 4; ++i) {
        uint4 u = dp[lane + 32 * i];
        const __half2* hp = (const __half2*)&u;
        #pragma unroll
        for (int p = 0; p < 4; ++p) {
            float2 f = __half22float2(hp[p]);
            v[8 * i + 2 * p]     = f.x;
            v[8 * i + 2 * p + 1] = f.y;
            vmin = fminf(vmin, fminf(f.x, f.y));
        }
    }
    #pragma unroll
    for (int o = 16; o; o >>= 1) vmin = fminf(vmin, __shfl_xor_sync(~0u, vmin, o));

    const float thresh = vmin + MARGIN;
    unsigned mask = 0;
    #pragma unroll
    for (int s = 0; s < 32; ++s)
        if (v[s] <= thresh) mask |= 1u << s;

    // residual in registers (used by rescore AND update)
    const float4* rrp = (const float4*)(R + (size_t)token * Dd);
    float4 rr[4];
    #pragma unroll
    for (int j = 0; j < 4; ++j) rr[j] = rrp[lane + 32 * j];

    float bd = 3.4e38f;
    int   bn = 1 << 30;

    while (true) {
        unsigned has = __ballot_sync(~0u, mask != 0);
        if (!has) break;
        int leader = __ffs(has) - 1;
        int s = 0;
        if (lane == leader) { s = __ffs(mask) - 1; mask &= mask - 1; }
        s = __shfl_sync(~0u, s, leader);
        const int n = 8 * (leader + 32 * (s >> 3)) + (s & 7);

        const float4* cc4 = (const float4*)(C + (size_t)n * Dd);
        float ssum = 0.0f;
        #pragma unroll
        for (int t = 0; t < 4; ++t) {
            float4 b = cc4[lane + 32 * t];
            ssum += rr[t].x * b.x + rr[t].y * b.y + rr[t].z * b.z + rr[t].w * b.w;
        }
        #pragma unroll
        for (int o = 16; o; o >>= 1) ssum += __shfl_xor_sync(~0u, ssum, o);

        float d = fmaf(-2.0f, ssum, __ldg(c2 + n));
        if (d < bd || (d == bd && n < bn)) { bd = d; bn = n; }
    }

    // fused update (residual already in rr)
    const float4* cp = (const float4*)(C + (size_t)bn * Dd);
    float4* rp = (float4*)(R + (size_t)token * Dd);
    uint32_t* r8 = (uint32_t*)(R8w + (size_t)token * Dd);
    float lsum = 0.0f, mx = 0.0f;
    float4 nrv[4];
    #pragma unroll
    for (int j = 0; j < 4; ++j) {
        float4 cv = cp[lane + 32 * j];
        float4 nr = make_float4(rr[j].x - cv.x, rr[j].y - cv.y,
                                rr[j].z - cv.z, rr[j].w - cv.w);
        nrv[j] = nr;
        rp[lane + 32 * j] = nr;
        lsum += nr.x * nr.x + nr.y * nr.y + nr.z * nr.z + nr.w * nr.w;
        mx = fmaxf(mx, max4abs(nr));
    }
    #pragma unroll
    for (int o = 16; o; o >>= 1) {
        lsum += __shfl_xor_sync(~0u, lsum, o);
        mx = fmaxf(mx, __shfl_xor_sync(~0u, mx, o));
    }
    const float inv = mx > 0.0f ? 127.0f / mx : 0.0f;
    #pragma unroll
    for (int j = 0; j < 4; ++j)
        r8[lane + 32 * j] = pack_s8(nrv[j], inv);
    if (lane == 0) {
        scaleAw[token] = mx / 127.0f;
        out_idx[(size_t)token * Qq + qstage] = (float)bn;
        atomicAdd(loss, lsum);
    }
}

// ---------------------------------------------------------------------------
// Final: quantized_out = x - residual_final  (one pass)
// ---------------------------------------------------------------------------
__global__ void final_out_kernel(const float4* __restrict__ x,
                                 const float4* __restrict__ residual,
                                 float4* __restrict__ out, int n4)
{
    int i = blockIdx.x * 256 + threadIdx.x;
    if (i < n4) {
        float4 a = x[i], r = residual[i];
        out[i] = make_float4(a.x - r.x, a.y - r.y, a.z - r.z, a.w - r.w);
    }
}

// Tail outputs: all_expired (zeros) then all_losses (mean over B*S*D)
__global__ void finalize_kernel(float* __restrict__ out, const float* __restrict__ loss)
{
    const size_t base = (size_t)Mm * Dd + (size_t)Mm * Qq;
    int t = threadIdx.x;
    if (t < Qq)
        out[base + t] = 0.0f;
    else if (t < 2 * Qq)
        out[base + Qq + (t - Qq)] = loss[t - Qq] * (1.0f / ((float)Mm * (float)Dd));
}

// ---------------------------------------------------------------------------
extern "C" void kernel_launch(void* const* d_in, const int* in_sizes, int n_in,
                              void* d_out, int out_size)
{
    const float* x  = (const float*)d_in[0];   // [B,S,D] f32
    const float* cb = (const float*)d_in[1];   // [Q,K,D] f32
    float* out = (float*)d_out;

    float* residual;   cudaGetSymbolAddress((void**)&residual, g_residual);
    int8_t* res8;      cudaGetSymbolAddress((void**)&res8,     g_res8);
    int8_t* cb8;       cudaGetSymbolAddress((void**)&cb8,      g_cb8);
    float* scaleA;     cudaGetSymbolAddress((void**)&scaleA,   g_scaleA);
    float* scaleB;     cudaGetSymbolAddress((void**)&scaleB,   g_scaleB);
    __half* dist;      cudaGetSymbolAddress((void**)&dist,     g_dist);
    float* c2;         cudaGetSymbolAddress((void**)&c2,       g_c2);
    float* loss;       cudaGetSymbolAddress((void**)&loss,     g_loss);

    // one-time resources (created on the first, uncaptured, correctness call)
    static cudaStream_t s2 = nullptr;
    static cudaEvent_t  evF = nullptr, evJ = nullptr;
    if (!s2) {
        cudaStreamCreateWithFlags(&s2, cudaStreamNonBlocking);
        cudaEventCreateWithFlags(&evF, cudaEventDisableTiming);
        cudaEventCreateWithFlags(&evJ, cudaEventDisableTiming);
        cudaFuncSetAttribute(gemm_dist_kernel,
                             cudaFuncAttributeMaxDynamicSharedMemorySize,
                             GEMM_SMEM);
    }

    // shared setup on the capture (default) stream
    cudaMemsetAsync(loss, 0, Qq * sizeof(float));
    init_q_kernel<<<Mm / 8, 256>>>(x, residual, res8, scaleA);
    conv_q_kernel<<<Qq * Kk / 8, 256>>>(cb, cb8, scaleB, c2);

    // fork: half H1 chain runs on s2
    cudaEventRecord(evF, 0);
    cudaStreamWaitEvent(s2, evF, 0);

    const size_t offE = (size_t)HALF_M * Dd;   // element offset of half 1
    float* out_idx = out + (size_t)Mm * Dd;

    for (int q = 0; q < Qq; ++q) {
        const float* Cq = cb + (size_t)q * Kk * Dd;
        const int8_t* Cq8 = cb8 + (size_t)q * Kk * Dd;
        dim3 grid(HALF_M / 128, Kk / 128);

        // half 0 on default stream
        gemm_dist_kernel<<<grid, 256, GEMM_SMEM, 0>>>(
            res8, Cq8, scaleA, scaleB + q * Kk, c2 + q * Kk, dist);
        refine_update_kernel<<<HALF_M / 8, 256, 0, 0>>>(
            dist, residual, res8, scaleA, Cq, c2 + q * Kk, out_idx,
            loss + q, q);

        // half 1 on s2
        gemm_dist_kernel<<<grid, 256, GEMM_SMEM, s2>>>(
            res8 + offE, Cq8, scaleA + HALF_M, scaleB + q * Kk,
            c2 + q * Kk, dist + (size_t)HALF_M * Kk);
        refine_update_kernel<<<HALF_M / 8, 256, 0, s2>>>(
            dist + (size_t)HALF_M * Kk, residual + offE, res8 + offE,
            scaleA + HALF_M, Cq, c2 + q * Kk,
            out_idx + (size_t)HALF_M * Qq, loss + q, q);
    }

    // join
    cudaEventRecord(evJ, s2);
    cudaStreamWaitEvent(0, evJ, 0);

    final_out_kernel<<<Mm * Dd / 4 / 256, 256>>>((const float4*)x,
                                                 (const float4*)residual,
                                                 (float4*)out, Mm * Dd / 4);
    finalize_kernel<<<1, 2 * Qq>>>(out, loss);
}

// round 16
// speedup vs baseline: 1.9623x; 1.9623x over previous
#include <cuda_runtime.h>
#include <cuda_fp16.h>
#include <cstdint>

// Problem constants
#define Bb 8
#define Ss 2048
#define Dd 512
#define Qq 8
#define Kk 1024
#define Mm (Bb * Ss)   // 16384 tokens
#define QUART_M (Mm / 4)
#define NCHAIN 4
#define MARGIN 8.0f

// Scratch (no cudaMalloc allowed)
__device__ float   g_residual[Mm * Dd];   // 32 MB fp32 residual
__device__ __half  g_res16[Mm * Dd];      // 16 MB fp16 residual
__device__ __half  g_cb16[Qq * Kk * Dd];  //  8 MB fp16 codebooks
__device__ __half  g_dist[Mm * Kk];       // 32 MB approx distances (fp16)
__device__ float   g_c2[Qq * Kk];
__device__ float   g_loss[Qq];

// ---------------------------------------------------------------------------
// helpers
// ---------------------------------------------------------------------------
__device__ __forceinline__ uint32_t smem_u32(const void* p) {
    uint32_t a;
    asm("{ .reg .u64 t; cvta.to.shared.u64 t, %1; cvt.u32.u64 %0, t; }"
        : "=r"(a) : "l"(p));
    return a;
}
__device__ __forceinline__ void cp16(uint32_t sa, const void* g) {
    asm volatile("cp.async.cg.shared.global [%0], [%1], 16;"
                 :: "r"(sa), "l"(g) : "memory");
}
__device__ __forceinline__ void cp_commit() {
    asm volatile("cp.async.commit_group;" ::: "memory");
}
__device__ __forceinline__ void cp_wait0() {
    asm volatile("cp.async.wait_group 0;" ::: "memory");
}
__device__ __forceinline__ void ldsm4(uint32_t* r, uint32_t addr) {
    asm volatile("ldmatrix.sync.aligned.m8n8.x4.shared.b16 {%0,%1,%2,%3}, [%4];"
                 : "=r"(r[0]), "=r"(r[1]), "=r"(r[2]), "=r"(r[3])
                 : "r"(addr));
}
// fp16 inputs, fp16 accumulators (2 x b32 regs hold 4 halves)
__device__ __forceinline__ void mma_f16acc(uint32_t* c, const uint32_t* a,
                                           uint32_t b0, uint32_t b1) {
    asm volatile(
        "mma.sync.aligned.m16n8k16.row.col.f16.f16.f16.f16 "
        "{%0,%1}, {%2,%3,%4,%5}, {%6,%7}, {%0,%1};"
        : "+r"(c[0]), "+r"(c[1])
        : "r"(a[0]), "r"(a[1]), "r"(a[2]), "r"(a[3]), "r"(b0), "r"(b1));
}

// ---------------------------------------------------------------------------
// init: residual=x (fp32), res16=fp16(x)
// ---------------------------------------------------------------------------
__global__ void init_kernel(const float4* __restrict__ x,
                            float4* __restrict__ residual,
                            __half2* __restrict__ res16, int n4)
{
    int i = blockIdx.x * 256 + threadIdx.x;
    if (i < n4) {
        float4 v = x[i];
        residual[i] = v;
        res16[2 * i]     = __floats2half2_rn(v.x, v.y);
        res16[2 * i + 1] = __floats2half2_rn(v.z, v.w);
    }
}

// fp32 -> fp16 codebook convert
__global__ void conv_kernel(const float4* __restrict__ in,
                            __half2* __restrict__ out, int n4)
{
    int i = blockIdx.x * 256 + threadIdx.x;
    if (i < n4) {
        float4 v = in[i];
        out[2 * i]     = __floats2half2_rn(v.x, v.y);
        out[2 * i + 1] = __floats2half2_rn(v.z, v.w);
    }
}

// ---------------------------------------------------------------------------
// c2[q][k] = ||codebook[q][k]||^2  — one warp per row (fp32 exact)
// ---------------------------------------------------------------------------
__global__ void c2_kernel(const float* __restrict__ codebooks, float* __restrict__ c2)
{
    int row  = blockIdx.x * 8 + (threadIdx.x >> 5);
    int lane = threadIdx.x & 31;
    const float4* p = (const float4*)(codebooks + (size_t)row * Dd);
    float s = 0.0f;
    #pragma unroll 4
    for (int i = lane; i < Dd / 4; i += 32) {
        float4 v = p[i];
        s += v.x * v.x + v.y * v.y + v.z * v.z + v.w * v.w;
    }
    #pragma unroll
    for (int off = 16; off; off >>= 1) s += __shfl_down_sync(0xffffffffu, s, off);
    if (lane == 0) c2[row] = s;
}

// ---------------------------------------------------------------------------
// fp16 mma.sync GEMM (fp16 acc) -> approx distances (fp16 stores).
// CTA 128x128, BK=64, 8 warps of 32x64, double-buffered cp.async, one sync
// per k-tile, fragment loads software-pipelined across the s-loop.
// (operates on a token-quarter: A16/dist pointers pre-offset by the caller)
// ---------------------------------------------------------------------------
#define GEMM_SMEM 65536   // 2 bufs * (A 16KB + B 16KB)

__global__ __launch_bounds__(256, 2)
void gemm_dist_kernel(const __half* __restrict__ A16,
                      const __half* __restrict__ B16,
                      const float* __restrict__ c2,
                      __half* __restrict__ dist)
{
    extern __shared__ char sm[];
    const uint32_t smb   = smem_u32(sm);
    const uint32_t Abase = smb;           // [2][16384]
    const uint32_t Bbase = smb + 32768;   // [2][16384]

    const int tid  = threadIdx.x;
    const int lane = tid & 31;
    const int warp = tid >> 5;
    const int bm = blockIdx.x * 128;
    const int bn = blockIdx.y * 128;
    const int wm = (warp & 3) * 32;
    const int wn = (warp >> 2) * 64;

    const char* gA = (const char*)(A16 + (size_t)bm * Dd);
    const char* gB = (const char*)(B16 + (size_t)bn * Dd);

    uint32_t acc[2][8][2];
    #pragma unroll
    for (int mi = 0; mi < 2; ++mi)
        #pragma unroll
        for (int ni = 0; ni < 8; ++ni) { acc[mi][ni][0] = 0u; acc[mi][ni][1] = 0u; }

    // precomputed fragment row addresses (buf-relative)
    uint32_t arow[2], brow[4];
    #pragma unroll
    for (int mi = 0; mi < 2; ++mi) {
        int row = wm + mi * 16 + (lane & 15);
        arow[mi] = Abase + row * 128 + (((lane >> 4) ^ (row & 7)) * 16);
    }
    #pragma unroll
    for (int nj = 0; nj < 4; ++nj) {
        int row = wn + nj * 16 + (lane & 15);
        brow[nj] = Bbase + row * 128 + (((lane >> 4) ^ (row & 7)) * 16);
    }

    #define LOAD_TILE(kt, buf)                                                  \
        {                                                                       \
            _Pragma("unroll")                                                   \
            for (int i = 0; i < 4; ++i) {                                       \
                int u = tid + 256 * i;                                          \
                int row = u >> 3, ch = u & 7;                                   \
                uint32_t so = (uint32_t)(row * 128 + ((ch ^ (row & 7)) * 16));  \
                size_t go = (size_t)row * (Dd * 2) + (kt) * 128 + ch * 16;      \
                cp16(Abase + (buf) * 16384 + so, gA + go);                      \
                cp16(Bbase + (buf) * 16384 + so, gB + go);                      \
            }                                                                   \
            cp_commit();                                                        \
        }

    #define LOAD_FRAGS(s, boff, areg, breg)                                     \
        {                                                                       \
            const uint32_t sx = (uint32_t)((s) * 2) << 4;                       \
            ldsm4(areg[0], (arow[0] ^ sx) + (boff));                            \
            ldsm4(areg[1], (arow[1] ^ sx) + (boff));                            \
            ldsm4(breg[0], (brow[0] ^ sx) + (boff));                            \
            ldsm4(breg[1], (brow[1] ^ sx) + (boff));                            \
            ldsm4(breg[2], (brow[2] ^ sx) + (boff));                            \
            ldsm4(breg[3], (brow[3] ^ sx) + (boff));                            \
        }

    LOAD_TILE(0, 0);

    uint32_t a[2][2][4], b[2][4][4];

    for (int kt = 0; kt < 8; ++kt) {
        const int buf = kt & 1;
        const uint32_t boff = (uint32_t)buf * 16384;
        cp_wait0();
        __syncthreads();
        if (kt < 7) LOAD_TILE(kt + 1, buf ^ 1);

        LOAD_FRAGS(0, boff, a[0], b[0]);
        #pragma unroll
        for (int s = 0; s < 4; ++s) {
            const int cur = s & 1, nxt = cur ^ 1;
            if (s < 3) LOAD_FRAGS(s + 1, boff, a[nxt], b[nxt]);
            #pragma unroll
            for (int mi = 0; mi < 2; ++mi)
                #pragma unroll
                for (int ni = 0; ni < 8; ++ni)
                    mma_f16acc(acc[mi][ni], a[cur][mi],
                               b[cur][ni >> 1][ni & 1],
                               b[cur][ni >> 1][(ni & 1) + 2]);
        }
    }

    // epilogue: d = c2[n] - 2*acc (acc fp16 -> fp32), fp16 stores
    const int g = lane >> 2, t4 = lane & 3;
    #pragma unroll
    for (int mi = 0; mi < 2; ++mi) {
        const int m0 = bm + wm + mi * 16 + g;
        #pragma unroll
        for (int ni = 0; ni < 8; ++ni) {
            const int n = bn + wn + ni * 8 + 2 * t4;
            float2 cc = *(const float2*)(c2 + n);
            float2 f0 = __half22float2(*(__half2*)&acc[mi][ni][0]);  // rows m0
            float2 f1 = __half22float2(*(__half2*)&acc[mi][ni][1]);  // rows m0+8
            __half2 h0 = __floats2half2_rn(fmaf(-2.0f, f0.x, cc.x),
                                           fmaf(-2.0f, f0.y, cc.y));
            __half2 h1 = __floats2half2_rn(fmaf(-2.0f, f1.x, cc.x),
                                           fmaf(-2.0f, f1.y, cc.y));
            *(__half2*)(dist + (size_t)m0 * Kk + n)       = h0;
            *(__half2*)(dist + (size_t)(m0 + 8) * Kk + n) = h1;
        }
    }
    #undef LOAD_TILE
    #undef LOAD_FRAGS
}

// ---------------------------------------------------------------------------
// Fused refine + update: warp per token (pointers pre-offset to token slice).
// ---------------------------------------------------------------------------
__global__ __launch_bounds__(256)
void refine_update_kernel(const __half* __restrict__ dist,
                          float* __restrict__ R,
                          __half* __restrict__ R16w,
                          const float* __restrict__ C,
                          const float* __restrict__ c2,
                          float* __restrict__ out_idx,
                          float* __restrict__ loss,
                          int qstage)
{
    const int warp = threadIdx.x >> 5, lane = threadIdx.x & 31;
    const int token = blockIdx.x * 8 + warp;

    // scan fp16 distances: 4 x uint4 per lane = 32 halves
    const uint4* dp = (const uint4*)(dist + (size_t)token * Kk);
    float v[32];
    float vmin = 3.4e38f;
    #pragma unroll
    for (int i = 0; i < 4; ++i) {
        uint4 u = dp[lane + 32 * i];
        const __half2* hp = (const __half2*)&u;
        #pragma unroll
        for (int p = 0; p < 4; ++p) {
            float2 f = __half22float2(hp[p]);
            v[8 * i + 2 * p]     = f.x;
            v[8 * i + 2 * p + 1] = f.y;
            vmin = fminf(vmin, fminf(f.x, f.y));
        }
    }
    #pragma unroll
    for (int o = 16; o; o >>= 1) vmin = fminf(vmin, __shfl_xor_sync(~0u, vmin, o));

    const float thresh = vmin + MARGIN;
    unsigned mask = 0;
    #pragma unroll
    for (int s = 0; s < 32; ++s)
        if (v[s] <= thresh) mask |= 1u << s;

    // residual in registers (used by rescore AND update)
    const float4* rrp = (const float4*)(R + (size_t)token * Dd);
    float4 rr[4];
    #pragma unroll
    for (int j = 0; j < 4; ++j) rr[j] = rrp[lane + 32 * j];

    float bd = 3.4e38f;
    int   bn = 1 << 30;

    while (true) {
        unsigned has = __ballot_sync(~0u, mask != 0);
        if (!has) break;
        int leader = __ffs(has) - 1;
        int s = 0;
        if (lane == leader) { s = __ffs(mask) - 1; mask &= mask - 1; }
        s = __shfl_sync(~0u, s, leader);
        // value v[s] of lane `leader` is code n = 8*(leader + 32*(s>>3)) + (s&7)
        const int n = 8 * (leader + 32 * (s >> 3)) + (s & 7);

        const float4* cc4 = (const float4*)(C + (size_t)n * Dd);
        float ssum = 0.0f;
        #pragma unroll
        for (int t = 0; t < 4; ++t) {
            float4 b = cc4[lane + 32 * t];
            ssum += rr[t].x * b.x + rr[t].y * b.y + rr[t].z * b.z + rr[t].w * b.w;
        }
        #pragma unroll
        for (int o = 16; o; o >>= 1) ssum += __shfl_xor_sync(~0u, ssum, o);

        float d = fmaf(-2.0f, ssum, __ldg(c2 + n));
        if (d < bd || (d == bd && n < bn)) { bd = d; bn = n; }
    }

    // fused update (residual already in rr)
    const float4* cp = (const float4*)(C + (size_t)bn * Dd);
    float4* rp = (float4*)(R + (size_t)token * Dd);
    __half2* r16p = (__half2*)(R16w + (size_t)token * Dd);
    float lsum = 0.0f;
    #pragma unroll
    for (int j = 0; j < 4; ++j) {
        float4 cv = cp[lane + 32 * j];
        float4 nr = make_float4(rr[j].x - cv.x, rr[j].y - cv.y,
                                rr[j].z - cv.z, rr[j].w - cv.w);
        rp[lane + 32 * j] = nr;
        r16p[2 * (lane + 32 * j)]     = __floats2half2_rn(nr.x, nr.y);
        r16p[2 * (lane + 32 * j) + 1] = __floats2half2_rn(nr.z, nr.w);
        lsum += nr.x * nr.x + nr.y * nr.y + nr.z * nr.z + nr.w * nr.w;
    }
    #pragma unroll
    for (int o = 16; o; o >>= 1) lsum += __shfl_xor_sync(~0u, lsum, o);
    if (lane == 0) {
        out_idx[(size_t)token * Qq + qstage] = (float)bn;
        atomicAdd(loss, lsum);
    }
}

// ---------------------------------------------------------------------------
// Final: quantized_out = x - residual_final  (one pass)
// ---------------------------------------------------------------------------
__global__ void final_out_kernel(const float4* __restrict__ x,
                                 const float4* __restrict__ residual,
                                 float4* __restrict__ out, int n4)
{
    int i = blockIdx.x * 256 + threadIdx.x;
    if (i < n4) {
        float4 a = x[i], r = residual[i];
        out[i] = make_float4(a.x - r.x, a.y - r.y, a.z - r.z, a.w - r.w);
    }
}

// Tail outputs: all_expired (zeros) then all_losses (mean over B*S*D)
__global__ void finalize_kernel(float* __restrict__ out, const float* __restrict__ loss)
{
    const size_t base = (size_t)Mm * Dd + (size_t)Mm * Qq;
    int t = threadIdx.x;
    if (t < Qq)
        out[base + t] = 0.0f;
    else if (t < 2 * Qq)
        out[base + Qq + (t - Qq)] = loss[t - Qq] * (1.0f / ((float)Mm * (float)Dd));
}

// ---------------------------------------------------------------------------
extern "C" void kernel_launch(void* const* d_in, const int* in_sizes, int n_in,
                              void* d_out, int out_size)
{
    const float* x  = (const float*)d_in[0];   // [B,S,D] f32
    const float* cb = (const float*)d_in[1];   // [Q,K,D] f32
    float* out = (float*)d_out;

    float* residual;   cudaGetSymbolAddress((void**)&residual, g_residual);
    __half* res16;     cudaGetSymbolAddress((void**)&res16,    g_res16);
    __half* cb16;      cudaGetSymbolAddress((void**)&cb16,     g_cb16);
    __half* dist;      cudaGetSymbolAddress((void**)&dist,     g_dist);
    float* c2;         cudaGetSymbolAddress((void**)&c2,       g_c2);
    float* loss;       cudaGetSymbolAddress((void**)&loss,     g_loss);

    // one-time resources (created on the first, uncaptured, correctness call)
    static cudaStream_t st[NCHAIN] = {nullptr, nullptr, nullptr, nullptr};
    static cudaEvent_t  evF = nullptr;
    static cudaEvent_t  evJ[NCHAIN] = {nullptr, nullptr, nullptr, nullptr};
    if (!st[1]) {
        st[0] = 0;   // capture/default stream
        for (int c = 1; c < NCHAIN; ++c)
            cudaStreamCreateWithFlags(&st[c], cudaStreamNonBlocking);
        cudaEventCreateWithFlags(&evF, cudaEventDisableTiming);
        for (int c = 1; c < NCHAIN; ++c)
            cudaEventCreateWithFlags(&evJ[c], cudaEventDisableTiming);
        cudaFuncSetAttribute(gemm_dist_kernel,
                             cudaFuncAttributeMaxDynamicSharedMemorySize,
                             GEMM_SMEM);
    }

    // shared setup on the capture (default) stream
    cudaMemsetAsync(loss, 0, Qq * sizeof(float));
    init_kernel<<<Mm * Dd / 4 / 256, 256>>>((const float4*)x, (float4*)residual,
                                            (__half2*)res16, Mm * Dd / 4);
    conv_kernel<<<(Qq * Kk * Dd / 4 + 255) / 256, 256>>>((const float4*)cb,
                                                         (__half2*)cb16,
                                                         Qq * Kk * Dd / 4);
    c2_kernel<<<Qq * Kk / 8, 256>>>(cb, c2);

    // fork
    cudaEventRecord(evF, 0);
    for (int c = 1; c < NCHAIN; ++c) cudaStreamWaitEvent(st[c], evF, 0);

    float* out_idx = out + (size_t)Mm * Dd;

    for (int q = 0; q < Qq; ++q) {
        const float* Cq = cb + (size_t)q * Kk * Dd;
        const __half* Cq16 = cb16 + (size_t)q * Kk * Dd;
        dim3 grid(QUART_M / 128, Kk / 128);

        for (int c = 0; c < NCHAIN; ++c) {
            const size_t tOff = (size_t)c * QUART_M;       // token offset
            const size_t eOff = tOff * Dd;                 // element offset
            gemm_dist_kernel<<<grid, 256, GEMM_SMEM, st[c]>>>(
                res16 + eOff, Cq16, c2 + q * Kk, dist + tOff * Kk);
            refine_update_kernel<<<QUART_M / 8, 256, 0, st[c]>>>(
                dist + tOff * Kk, residual + eOff, res16 + eOff,
                Cq, c2 + q * Kk, out_idx + tOff * Qq, loss + q, q);
        }
    }

    // join
    for (int c = 1; c < NCHAIN; ++c) {
        cudaEventRecord(evJ[c], st[c]);
        cudaStreamWaitEvent(0, evJ[c], 0);
    }

    final_out_kernel<<<Mm * Dd / 4 / 256, 256>>>((const float4*)x,
                                                 (const float4*)residual,
                                                 (float4*)out, Mm * Dd / 4);
    finalize_kernel<<<1, 2 * Qq>>>(out, loss);
}